// round 13
// baseline (speedup 1.0000x reference)
#include <cuda_runtime.h>
#include <cuda_bf16.h>
#include <math.h>
#include <stdint.h>

#define BB 2
#define SS 2048
#define FF_IN 64
#define EE 512
#define HH 8
#define DH 64
#define LL 4
#define FFN 2048
#define MM (BB * SS)
#define ATTN_SCALE 0.044194173824159216f

// ---------------- helpers ----------------
__device__ __forceinline__ uint32_t smem_u32(const void* p) {
    uint32_t a;
    asm("{ .reg .u64 t; cvta.to.shared.u64 t, %1; cvt.u32.u64 %0, t; }" : "=r"(a) : "l"(p));
    return a;
}
#define SWZ128(o) ((o) ^ (((o) >> 3) & 0x70))

__device__ __forceinline__ void cp16(uint32_t s, const void* g) {
    asm volatile("cp.async.cg.shared.global [%0], [%1], 16;" :: "r"(s), "l"(g) : "memory");
}
#define CP_COMMIT() asm volatile("cp.async.commit_group;" ::: "memory")

__device__ __forceinline__ void ldsm4(uint32_t* d, uint32_t a) {
    asm volatile("ldmatrix.sync.aligned.m8n8.x4.shared.b16 {%0,%1,%2,%3}, [%4];"
                 : "=r"(d[0]), "=r"(d[1]), "=r"(d[2]), "=r"(d[3]) : "r"(a));
}
__device__ __forceinline__ void mma_bf16(float* c, const uint32_t* a, const uint32_t* b) {
    asm volatile("mma.sync.aligned.m16n8k16.row.col.f32.bf16.bf16.f32 "
        "{%0,%1,%2,%3}, {%4,%5,%6,%7}, {%8,%9}, {%0,%1,%2,%3};"
        : "+f"(c[0]), "+f"(c[1]), "+f"(c[2]), "+f"(c[3])
        : "r"(a[0]), "r"(a[1]), "r"(a[2]), "r"(a[3]), "r"(b[0]), "r"(b[1]));
}

__device__ __forceinline__ void split_hl(float f, uint16_t& h, uint16_t& l) {
    __nv_bfloat16 hb = __float2bfloat16(f);
    __nv_bfloat16 lb = __float2bfloat16(f - __bfloat162float(hb));
    h = __bfloat16_as_ushort(hb); l = __bfloat16_as_ushort(lb);
}
__device__ __forceinline__ uint32_t pack2(uint16_t a, uint16_t b) {
    return (uint32_t)a | ((uint32_t)b << 16);
}
__device__ __forceinline__ void store_hl4(__nv_bfloat16* rowp, int col,
                                          float v0, float v1, float v2, float v3) {
    int b = col >> 5, w = col & 31;
    uint16_t h0,l0,h1,l1,h2,l2,h3,l3;
    split_hl(v0,h0,l0); split_hl(v1,h1,l1); split_hl(v2,h2,l2); split_hl(v3,h3,l3);
    *(uint2*)(rowp + b*64 + w)      = make_uint2(pack2(h0,h1), pack2(h2,h3));
    *(uint2*)(rowp + b*64 + 32 + w) = make_uint2(pack2(l0,l1), pack2(l2,l3));
}
__device__ __forceinline__ void store_hl2(__nv_bfloat16* rowp, int col, float v0, float v1) {
    int b = col >> 5, w = col & 31;
    uint16_t h0,l0,h1,l1;
    split_hl(v0,h0,l0); split_hl(v1,h1,l1);
    *(uint32_t*)(rowp + b*64 + w)      = pack2(h0,h1);
    *(uint32_t*)(rowp + b*64 + 32 + w) = pack2(l0,l1);
}

// ---------------- scratch ----------------
__device__ float g_X[MM * EE];
__device__ float g_P[MM * EE];
__device__ float g_bqkv[LL * 1536];
__device__ __nv_bfloat16 g_XHL[MM * 2 * EE];
__device__ __nv_bfloat16 g_ATTHL[MM * 2 * EE];
__device__ __nv_bfloat16 g_H1HL[MM * 2 * FFN];
__device__ __nv_bfloat16 g_Qh[MM * EE], g_Ql[MM * EE];
__device__ __nv_bfloat16 g_Kh[MM * EE], g_Kl[MM * EE];
__device__ __nv_bfloat16 g_VhT[BB * HH * DH * SS], g_VlT[BB * HH * DH * SS];
__device__ __nv_bfloat16 g_QKVWHL[LL * 1536 * 2 * EE];
__device__ __nv_bfloat16 g_WOHL[LL * EE * 2 * EE];
__device__ __nv_bfloat16 g_W1HL[LL * FFN * 2 * EE];
__device__ __nv_bfloat16 g_W2HL[LL * EE * 2 * FFN];

// ---------------- merged weight prep ----------------
__global__ __launch_bounds__(256) void prep_all(
    const float* __restrict__ Wq, const float* __restrict__ Wk,
    const float* __restrict__ Wv, const float* __restrict__ Wo,
    const float* __restrict__ W1, const float* __restrict__ W2,
    __nv_bfloat16* __restrict__ QKVWHL, __nv_bfloat16* __restrict__ WOHL,
    __nv_bfloat16* __restrict__ W1HL, __nv_bfloat16* __restrict__ W2HL)
{
    __shared__ float t[32][33];
    int bid = blockIdx.x, l = blockIdx.z;
    const float* W; __nv_bfloat16* D; int K, N, bx, by;
    if (bid < 1024) {
        int s = bid >> 8; bid &= 255;
        K = EE; N = EE; bx = bid & 15; by = bid >> 4;
        const float* srcs[4] = {Wq, Wk, Wv, Wo};
        W = srcs[s] + (size_t)l * EE * EE;
        D = (s < 3) ? QKVWHL + (size_t)l * 1536 * 2 * EE + (size_t)s * 512 * 2 * EE
                    : WOHL + (size_t)l * EE * 2 * EE;
    } else if (bid < 2048) {
        bid -= 1024;
        K = EE; N = FFN; bx = bid & 63; by = bid >> 6;
        W = W1 + (size_t)l * EE * FFN;
        D = W1HL + (size_t)l * FFN * 2 * EE;
    } else {
        bid -= 2048;
        K = FFN; N = EE; bx = bid & 15; by = bid >> 4;
        W = W2 + (size_t)l * FFN * EE;
        D = W2HL + (size_t)l * EE * 2 * FFN;
    }
    int k0 = by * 32, n0 = bx * 32;
    int tx = threadIdx.x, ty = threadIdx.y;
    #pragma unroll
    for (int i = 0; i < 4; i++)
        t[ty + i * 8][tx] = W[(size_t)(k0 + ty + i * 8) * N + n0 + tx];
    __syncthreads();
    int bofs = (k0 >> 5) * 64;
    #pragma unroll
    for (int i = 0; i < 4; i++) {
        int n = n0 + ty + i * 8;
        float v = t[tx][ty + i * 8];
        uint16_t h, lo; split_hl(v, h, lo);
        __nv_bfloat16* rp = D + (size_t)n * 2 * K + bofs;
        *(uint16_t*)(rp + tx)      = h;
        *(uint16_t*)(rp + 32 + tx) = lo;
    }
}

__global__ __launch_bounds__(256) void biascat_kernel(
    const float* __restrict__ bq, const float* __restrict__ bk,
    const float* __restrict__ bv, float* __restrict__ o)
{
    int i = blockIdx.x * 256 + threadIdx.x;
    if (i >= LL * 1536) return;
    int l = i / 1536, j = i - l * 1536;
    o[i] = (j < 512) ? bq[l * 512 + j] : (j < 1024) ? bk[l * 512 + j - 512] : bv[l * 512 + j - 1024];
}

// ---------------- HL HMMA GEMM (MT=1, 3-buffer, single bar per stage) ----------------
// Stage = 24KB (A 8KB + B 16KB), 3 buffers rotate; max warp skew 1 iter enforced
// by the post-wait barrier, so loads for s+1 (buf (s+1)%3) never collide with
// the slowest reader (buf s%3).
#define STB   24576
#define GSMEM (3 * STB)
template <int OUTQ>
__global__ __launch_bounds__(256, 2) void hl_gemm(
    const __nv_bfloat16* __restrict__ A, const __nv_bfloat16* __restrict__ B,
    const float* __restrict__ bias, void* __restrict__ Cout, int ldc, int K,
    __nv_bfloat16* __restrict__ qh, __nv_bfloat16* __restrict__ ql,
    __nv_bfloat16* __restrict__ kh, __nv_bfloat16* __restrict__ kl,
    __nv_bfloat16* __restrict__ vth, __nv_bfloat16* __restrict__ vtl)
{
    extern __shared__ char smem[];
    const uint32_t sb = smem_u32(smem);
    const int tid = threadIdx.x, lane = tid & 31, wid = tid >> 5;
    const int wm = (wid >> 1) * 16, wn = (wid & 1) * 64;
    const int cRow = blockIdx.y * 64, cCol = blockIdx.x * 128;
    const size_t rowbytes = (size_t)K * 4;
    const char* Abase = (const char*)(A + (size_t)cRow * 2 * K);
    const char* Bbase = (const char*)(B + (size_t)cCol * 2 * K);

    float acc[8][4];
    #pragma unroll
    for (int b = 0; b < 8; b++)
        #pragma unroll
        for (int c = 0; c < 4; c++) acc[b][c] = 0.f;

    uint32_t oA, oB4[4];
    {
        int row = wm + ((lane >> 3) & 1) * 8 + (lane & 7);
        oA = SWZ128((uint32_t)(row * 128 + (lane >> 4) * 16));
    }
    #pragma unroll
    for (int ng = 0; ng < 4; ng++) {
        int row = wn + ng * 16 + ((lane >> 4) & 1) * 8 + (lane & 7);
        oB4[ng] = SWZ128((uint32_t)(row * 128 + ((lane >> 3) & 1) * 16));
    }

    const int lr = tid >> 3, lc = (tid & 7) * 16;
    auto load_stage = [&](int s) {
        uint32_t dA = sb + (s % 3) * STB, dB = dA + 8192;
        size_t kb = (size_t)s * 128;
        #pragma unroll
        for (int i = 0; i < 2; i++) {
            int r = lr + i * 32;
            cp16(dA + SWZ128(r * 128 + lc), Abase + (size_t)r * rowbytes + kb + lc);
        }
        #pragma unroll
        for (int i = 0; i < 4; i++) {
            int r = lr + i * 32;
            cp16(dB + SWZ128(r * 128 + lc), Bbase + (size_t)r * rowbytes + kb + lc);
        }
    };

    const int NS = K / 32;
    load_stage(0); CP_COMMIT();
    for (int s = 0; s < NS; s++) {
        if (s + 1 < NS) {
            load_stage(s + 1); CP_COMMIT();
            asm volatile("cp.async.wait_group 1;" ::: "memory");
        } else {
            asm volatile("cp.async.wait_group 0;" ::: "memory");
        }
        __syncthreads();
        uint32_t sA = sb + (s % 3) * STB, sB = sA + 8192;
        #pragma unroll
        for (int c = 0; c < 2; c++) {
            const uint32_t ch = c * 32, cl = 64 + c * 32;
            uint32_t ah[4], al[4];
            ldsm4(ah, sA + (oA ^ ch));
            ldsm4(al, sA + (oA ^ cl));
            #pragma unroll
            for (int ng = 0; ng < 4; ng++) {
                uint32_t bh[4], bl[4];
                ldsm4(bh, sB + (oB4[ng] ^ ch));
                ldsm4(bl, sB + (oB4[ng] ^ cl));
                #pragma unroll
                for (int term = 0; term < 3; term++)
                    #pragma unroll
                    for (int t2 = 0; t2 < 2; t2++) {
                        int nt = ng * 2 + t2;
                        const uint32_t* aop = (term == 2) ? al : ah;
                        const uint32_t* bop = (term == 1) ? &bl[t2 * 2] : &bh[t2 * 2];
                        mma_bf16(acc[nt], aop, bop);
                    }
            }
        }
    }

    if (OUTQ == 2 && cCol >= 1024) {
        // V tile (64 rows): stage hi/lo [col][row], write transposed
        const int P = 68;
        uint16_t* shi = (uint16_t*)smem;
        uint16_t* slo = shi + 128 * P;
        __syncthreads();   // all warps done with last MMA buffer before reuse
        #pragma unroll
        for (int rp = 0; rp < 2; rp++) {
            int lrw = wm + rp * 8 + (lane >> 2);
            #pragma unroll
            for (int nt = 0; nt < 8; nt++) {
                int clw = wn + nt * 8 + (lane & 3) * 2;
                float2 bz = *(const float2*)(bias + cCol + clw);
                float v0 = acc[nt][rp * 2]     + bz.x;
                float v1 = acc[nt][rp * 2 + 1] + bz.y;
                uint16_t h0, l0, h1, l1;
                split_hl(v0, h0, l0); split_hl(v1, h1, l1);
                shi[clw * P + lrw] = h0; slo[clw * P + lrw] = l0;
                shi[(clw + 1) * P + lrw] = h1; slo[(clw + 1) * P + lrw] = l1;
            }
        }
        __syncthreads();
        int c = tid >> 1, rh = (tid & 1) * 32;
        int gcol = cCol - 1024 + c;
        int hh = gcol >> 6, d = gcol & 63;
        int b = cRow >> 11, s0 = (cRow & 2047) + rh;
        __nv_bfloat16* dh = vth + ((size_t)(b * HH + hh) * DH + d) * SS + s0;
        __nv_bfloat16* dl = vtl + ((size_t)(b * HH + hh) * DH + d) * SS + s0;
        const uint16_t* sh = shi + c * P + rh;
        const uint16_t* sl = slo + c * P + rh;
        #pragma unroll
        for (int i = 0; i < 8; i++) {
            *(uint2*)(dh + i * 4) = *(const uint2*)(sh + i * 4);
            *(uint2*)(dl + i * 4) = *(const uint2*)(sl + i * 4);
        }
        return;
    }

    #pragma unroll
    for (int rp = 0; rp < 2; rp++) {
        int row = cRow + wm + rp * 8 + (lane >> 2);
        #pragma unroll
        for (int nt = 0; nt < 8; nt++) {
            int col = cCol + wn + nt * 8 + (lane & 3) * 2;
            float2 bz = *(const float2*)(bias + col);
            float v0 = acc[nt][rp * 2]     + bz.x;
            float v1 = acc[nt][rp * 2 + 1] + bz.y;
            if (OUTQ == 1) {
                v0 = fmaxf(v0, 0.f); v1 = fmaxf(v1, 0.f);
                store_hl2((__nv_bfloat16*)Cout + (size_t)row * 2 * ldc, col, v0, v1);
            } else if (OUTQ == 2) {
                if (col < 512) {
                    float s0 = v0 * ATTN_SCALE, s1 = v1 * ATTN_SCALE;
                    uint16_t h0, l0, h1, l1;
                    split_hl(s0, h0, l0); split_hl(s1, h1, l1);
                    *(uint32_t*)(qh + (size_t)row * EE + col) = pack2(h0, h1);
                    *(uint32_t*)(ql + (size_t)row * EE + col) = pack2(l0, l1);
                } else {
                    int cc = col - 512;
                    uint16_t h0, l0, h1, l1;
                    split_hl(v0, h0, l0); split_hl(v1, h1, l1);
                    *(uint32_t*)(kh + (size_t)row * EE + cc) = pack2(h0, h1);
                    *(uint32_t*)(kl + (size_t)row * EE + cc) = pack2(l0, l1);
                }
            } else {
                *(float2*)((float*)Cout + (size_t)row * ldc + col) = make_float2(v0, v1);
            }
        }
    }
}

// ---------------- HMMA flash attention ----------------
#define ATTN_SMEM2 (98304 + 512)
__global__ __launch_bounds__(256, 2) void attn_hmma(
    const __nv_bfloat16* __restrict__ Qh, const __nv_bfloat16* __restrict__ Ql,
    const __nv_bfloat16* __restrict__ Kh, const __nv_bfloat16* __restrict__ Kl,
    const __nv_bfloat16* __restrict__ VhT, const __nv_bfloat16* __restrict__ VlT,
    const int* __restrict__ mask, __nv_bfloat16* __restrict__ ATTHL)
{
    extern __shared__ char smem[];
    const uint32_t sb = smem_u32(smem);
    int* Ms = (int*)(smem + 98304);
    const int tid = threadIdx.x, lane = tid & 31, wid = tid >> 5;
    const int bh = blockIdx.y, b = bh >> 3, h = bh & 7;
    const int qrow0 = blockIdx.x * 128;
    const int wr = wid * 16;

    uint32_t oQ, oKV[4];
    {
        int row = wr + ((lane >> 3) & 1) * 8 + (lane & 7);
        oQ = SWZ128((uint32_t)(row * 128 + (lane >> 4) * 16));
    }
    #pragma unroll
    for (int ng = 0; ng < 4; ng++) {
        int row = ng * 16 + ((lane >> 4) & 1) * 8 + (lane & 7);
        oKV[ng] = SWZ128((uint32_t)(row * 128 + ((lane >> 3) & 1) * 16));
    }

    {
        const char* qhp = (const char*)(Qh + (size_t)(b * SS + qrow0) * EE + h * DH);
        const char* qlp = (const char*)(Ql + (size_t)(b * SS + qrow0) * EE + h * DH);
        #pragma unroll
        for (int i = 0; i < 4; i++) {
            int id = tid + i * 256;
            int r = id >> 3, ck = (id & 7) * 16;
            cp16(sb +         SWZ128(r * 128 + ck), qhp + (size_t)r * 1024 + ck);
            cp16(sb + 16384 + SWZ128(r * 128 + ck), qlp + (size_t)r * 1024 + ck);
        }
    }
    auto load_stage = [&](int kt) {
        uint32_t st = sb + 32768 + (kt & 1) * 32768;
        const char* khp = (const char*)(Kh + (size_t)(b * SS + kt * 64) * EE + h * DH);
        const char* klp = (const char*)(Kl + (size_t)(b * SS + kt * 64) * EE + h * DH);
        const char* vhp = (const char*)(VhT + (size_t)bh * DH * SS + kt * 64);
        const char* vlp = (const char*)(VlT + (size_t)bh * DH * SS + kt * 64);
        #pragma unroll
        for (int i = 0; i < 2; i++) {
            int id = tid + i * 256;
            int r = id >> 3, ck = (id & 7) * 16;
            cp16(st +         SWZ128(r * 128 + ck), khp + (size_t)r * 1024 + ck);
            cp16(st + 8192  + SWZ128(r * 128 + ck), klp + (size_t)r * 1024 + ck);
            cp16(st + 16384 + SWZ128(r * 128 + ck), vhp + (size_t)r * (SS * 2) + ck);
            cp16(st + 24576 + SWZ128(r * 128 + ck), vlp + (size_t)r * (SS * 2) + ck);
        }
        if (tid < 64) Ms[(kt & 1) * 64 + tid] = mask[b * SS + kt * 64 + tid];
    };

    float m_i[2] = {-INFINITY, -INFINITY}, l_i[2] = {0.f, 0.f};
    float o_acc[8][4];
    #pragma unroll
    for (int nt = 0; nt < 8; nt++)
        #pragma unroll
        for (int c = 0; c < 4; c++) o_acc[nt][c] = 0.f;

    load_stage(0); CP_COMMIT();
    const int NT = SS / 64;
    for (int kt = 0; kt < NT; kt++) {
        if (kt + 1 < NT) {
            load_stage(kt + 1); CP_COMMIT();
            asm volatile("cp.async.wait_group 1;" ::: "memory");
        } else {
            asm volatile("cp.async.wait_group 0;" ::: "memory");
        }
        __syncthreads();
        const uint32_t st = sb + 32768 + (kt & 1) * 32768;
        const uint32_t sKh = st, sKl = st + 8192, sVh = st + 16384, sVl = st + 24576;

        float s_acc[8][4];
        #pragma unroll
        for (int nt = 0; nt < 8; nt++)
            #pragma unroll
            for (int c = 0; c < 4; c++) s_acc[nt][c] = 0.f;

        #pragma unroll
        for (int kc = 0; kc < 4; kc++) {
            const uint32_t bc = kc * 32;
            uint32_t qhf[4], qlf[4];
            ldsm4(qhf, sb +         (oQ ^ bc));
            ldsm4(qlf, sb + 16384 + (oQ ^ bc));
            #pragma unroll
            for (int ng = 0; ng < 4; ng++) {
                uint32_t khf[4], klf[4];
                ldsm4(khf, sKh + (oKV[ng] ^ bc));
                ldsm4(klf, sKl + (oKV[ng] ^ bc));
                #pragma unroll
                for (int term = 0; term < 3; term++)
                    #pragma unroll
                    for (int t2 = 0; t2 < 2; t2++) {
                        int nt = ng * 2 + t2;
                        const uint32_t* aop = (term == 2) ? qlf : qhf;
                        const uint32_t* bop = (term == 1) ? &klf[t2 * 2] : &khf[t2 * 2];
                        mma_bf16(s_acc[nt], aop, bop);
                    }
            }
        }

        const int t4 = (lane & 3) * 2;
        const int msb = (kt & 1) * 64;
        #pragma unroll
        for (int nt = 0; nt < 8; nt++) {
            if (Ms[msb + nt * 8 + t4] == 0)     { s_acc[nt][0] = -1e20f; s_acc[nt][2] = -1e20f; }
            if (Ms[msb + nt * 8 + t4 + 1] == 0) { s_acc[nt][1] = -1e20f; s_acc[nt][3] = -1e20f; }
        }

        #pragma unroll
        for (int r = 0; r < 2; r++) {
            float mx = -INFINITY;
            #pragma unroll
            for (int nt = 0; nt < 8; nt++)
                mx = fmaxf(mx, fmaxf(s_acc[nt][r * 2], s_acc[nt][r * 2 + 1]));
            mx = fmaxf(mx, __shfl_xor_sync(0xffffffffu, mx, 1));
            mx = fmaxf(mx, __shfl_xor_sync(0xffffffffu, mx, 2));
            float mnew = fmaxf(m_i[r], mx);
            float corr = __expf(m_i[r] - mnew);
            float rs = 0.f;
            #pragma unroll
            for (int nt = 0; nt < 8; nt++) {
                float p0 = __expf(s_acc[nt][r * 2] - mnew);
                float p1 = __expf(s_acc[nt][r * 2 + 1] - mnew);
                s_acc[nt][r * 2] = p0; s_acc[nt][r * 2 + 1] = p1;
                rs += p0 + p1;
            }
            rs += __shfl_xor_sync(0xffffffffu, rs, 1);
            rs += __shfl_xor_sync(0xffffffffu, rs, 2);
            l_i[r] = l_i[r] * corr + rs;
            m_i[r] = mnew;
            #pragma unroll
            for (int nt = 0; nt < 8; nt++) {
                o_acc[nt][r * 2] *= corr; o_acc[nt][r * 2 + 1] *= corr;
            }
        }

        #pragma unroll
        for (int kc = 0; kc < 4; kc++) {
            const uint32_t bc = kc * 32;
            uint32_t ph[4], pl[4];
            {
                uint16_t h0, l0, h1, l1;
                split_hl(s_acc[2 * kc][0], h0, l0); split_hl(s_acc[2 * kc][1], h1, l1);
                ph[0] = pack2(h0, h1); pl[0] = pack2(l0, l1);
                split_hl(s_acc[2 * kc][2], h0, l0); split_hl(s_acc[2 * kc][3], h1, l1);
                ph[1] = pack2(h0, h1); pl[1] = pack2(l0, l1);
                split_hl(s_acc[2 * kc + 1][0], h0, l0); split_hl(s_acc[2 * kc + 1][1], h1, l1);
                ph[2] = pack2(h0, h1); pl[2] = pack2(l0, l1);
                split_hl(s_acc[2 * kc + 1][2], h0, l0); split_hl(s_acc[2 * kc + 1][3], h1, l1);
                ph[3] = pack2(h0, h1); pl[3] = pack2(l0, l1);
            }
            #pragma unroll
            for (int ng = 0; ng < 4; ng++) {
                uint32_t vhf[4], vlf[4];
                ldsm4(vhf, sVh + (oKV[ng] ^ bc));
                ldsm4(vlf, sVl + (oKV[ng] ^ bc));
                #pragma unroll
                for (int term = 0; term < 3; term++)
                    #pragma unroll
                    for (int t2 = 0; t2 < 2; t2++) {
                        int nt = ng * 2 + t2;
                        const uint32_t* aop = (term == 2) ? pl : ph;
                        const uint32_t* bop = (term == 1) ? &vlf[t2 * 2] : &vhf[t2 * 2];
                        mma_bf16(o_acc[nt], aop, bop);
                    }
            }
        }
        __syncthreads();
    }

    const int g = lane >> 2;
    #pragma unroll
    for (int r = 0; r < 2; r++) {
        float inv = 1.f / l_i[r];
        int row = qrow0 + wr + g + r * 8;
        __nv_bfloat16* rp = ATTHL + (size_t)(b * SS + row) * 2 * EE;
        #pragma unroll
        for (int nt = 0; nt < 8; nt++) {
            int col = h * DH + nt * 8 + (lane & 3) * 2;
            store_hl2(rp, col, o_acc[nt][r * 2] * inv, o_acc[nt][r * 2 + 1] * inv);
        }
    }
}

// ---------------- embedding ----------------
__global__ __launch_bounds__(128) void embed_kernel(
    const float* __restrict__ seq, const float* __restrict__ W,
    const float* __restrict__ bias, const float* __restrict__ pos,
    float* __restrict__ X, __nv_bfloat16* __restrict__ XHL)
{
    int m = blockIdx.x, s = m & (SS - 1), tid = threadIdx.x;
    __shared__ float srow[FF_IN];
    if (tid < FF_IN) srow[tid] = seq[(size_t)m * FF_IN + tid];
    __syncthreads();
    int n = tid * 4;
    float4 acc = *(const float4*)(bias + n);
    float4 pv  = *(const float4*)(pos + (size_t)s * EE + n);
    acc.x += pv.x; acc.y += pv.y; acc.z += pv.z; acc.w += pv.w;
    #pragma unroll 8
    for (int f = 0; f < FF_IN; f++) {
        float sv = srow[f];
        float4 w = *(const float4*)(W + (size_t)f * EE + n);
        acc.x += sv * w.x; acc.y += sv * w.y; acc.z += sv * w.z; acc.w += sv * w.w;
    }
    *(float4*)(X + (size_t)m * EE + n) = acc;
    store_hl4(XHL + (size_t)m * 2 * EE, n, acc.x, acc.y, acc.z, acc.w);
}

// ---------------- residual + LN (2 rows per 256-thread block) ----------------
__global__ __launch_bounds__(256) void ln_kernel(
    const float* __restrict__ a, const float* __restrict__ br,
    const float* __restrict__ g, const float* __restrict__ be,
    float* __restrict__ out, __nv_bfloat16* __restrict__ xhl)
{
    int tid = threadIdx.x;
    int rloc = tid >> 7;
    int t = tid & 127;
    int m = blockIdx.x * 2 + rloc;
    size_t base = (size_t)m * EE + t * 4;
    float4 va = *(const float4*)(a + base);
    float4 vb = *(const float4*)(br + base);
    float x0 = va.x + vb.x, x1 = va.y + vb.y, x2 = va.z + vb.z, x3 = va.w + vb.w;
    float s = x0 + x1 + x2 + x3;
    float ss = x0 * x0 + x1 * x1 + x2 * x2 + x3 * x3;
    #pragma unroll
    for (int off = 16; off; off >>= 1) {
        s  += __shfl_xor_sync(0xffffffffu, s, off);
        ss += __shfl_xor_sync(0xffffffffu, ss, off);
    }
    __shared__ float red[2][8];
    int w = t >> 5;
    if ((t & 31) == 0) { red[rloc][w] = s; red[rloc][4 + w] = ss; }
    __syncthreads();
    s  = red[rloc][0] + red[rloc][1] + red[rloc][2] + red[rloc][3];
    ss = red[rloc][4] + red[rloc][5] + red[rloc][6] + red[rloc][7];
    float mean = s * (1.f / EE);
    float var  = ss * (1.f / EE) - mean * mean;
    float r = rsqrtf(var + 1e-5f);
    float4 gg = *(const float4*)(g + t * 4);
    float4 bb = *(const float4*)(be + t * 4);
    float4 o;
    o.x = (x0 - mean) * r * gg.x + bb.x;
    o.y = (x1 - mean) * r * gg.y + bb.y;
    o.z = (x2 - mean) * r * gg.z + bb.z;
    o.w = (x3 - mean) * r * gg.w + bb.w;
    *(float4*)(out + base) = o;
    if (xhl) store_hl4(xhl + (size_t)m * 2 * EE, t * 4, o.x, o.y, o.z, o.w);
}

// ---------------- launch ----------------
extern "C" void kernel_launch(void* const* d_in, const int* in_sizes, int n_in,
                              void* d_out, int out_size)
{
    const float* seq   = (const float*)d_in[0];
    const int*   mask  = (const int*)  d_in[1];
    const float* W_emb = (const float*)d_in[2];
    const float* b_emb = (const float*)d_in[3];
    const float* pos   = (const float*)d_in[4];
    const float* Wq    = (const float*)d_in[5];
    const float* bq    = (const float*)d_in[6];
    const float* Wk    = (const float*)d_in[7];
    const float* bk    = (const float*)d_in[8];
    const float* Wv    = (const float*)d_in[9];
    const float* bv    = (const float*)d_in[10];
    const float* Wo    = (const float*)d_in[11];
    const float* bo    = (const float*)d_in[12];
    const float* ln1g  = (const float*)d_in[13];
    const float* ln1b  = (const float*)d_in[14];
    const float* ln2g  = (const float*)d_in[15];
    const float* ln2b  = (const float*)d_in[16];
    const float* W1    = (const float*)d_in[17];
    const float* b1    = (const float*)d_in[18];
    const float* W2    = (const float*)d_in[19];
    const float* b2    = (const float*)d_in[20];
    float* out = (float*)d_out;

    float *X, *P, *bqkv;
    __nv_bfloat16 *XHL, *ATTHL, *H1HL, *QKVWHL, *WOHL, *W1HL, *W2HL;
    __nv_bfloat16 *Qh, *Ql, *Kh, *Kl, *VhT, *VlT;
    cudaGetSymbolAddress((void**)&X,     g_X);
    cudaGetSymbolAddress((void**)&P,     g_P);
    cudaGetSymbolAddress((void**)&bqkv,  g_bqkv);
    cudaGetSymbolAddress((void**)&XHL,   g_XHL);
    cudaGetSymbolAddress((void**)&ATTHL, g_ATTHL);
    cudaGetSymbolAddress((void**)&H1HL,  g_H1HL);
    cudaGetSymbolAddress((void**)&QKVWHL,g_QKVWHL);
    cudaGetSymbolAddress((void**)&WOHL,  g_WOHL);
    cudaGetSymbolAddress((void**)&W1HL,  g_W1HL);
    cudaGetSymbolAddress((void**)&W2HL,  g_W2HL);
    cudaGetSymbolAddress((void**)&Qh,    g_Qh);
    cudaGetSymbolAddress((void**)&Ql,    g_Ql);
    cudaGetSymbolAddress((void**)&Kh,    g_Kh);
    cudaGetSymbolAddress((void**)&Kl,    g_Kl);
    cudaGetSymbolAddress((void**)&VhT,   g_VhT);
    cudaGetSymbolAddress((void**)&VlT,   g_VlT);

    cudaFuncSetAttribute((const void*)hl_gemm<0>, cudaFuncAttributeMaxDynamicSharedMemorySize, GSMEM);
    cudaFuncSetAttribute((const void*)hl_gemm<1>, cudaFuncAttributeMaxDynamicSharedMemorySize, GSMEM);
    cudaFuncSetAttribute((const void*)hl_gemm<2>, cudaFuncAttributeMaxDynamicSharedMemorySize, GSMEM);
    cudaFuncSetAttribute((const void*)attn_hmma, cudaFuncAttributeMaxDynamicSharedMemorySize, ATTN_SMEM2);

    biascat_kernel<<<24, 256>>>(bq, bk, bv, bqkv);
    prep_all<<<dim3(3072, 1, LL), dim3(32, 8)>>>(Wq, Wk, Wv, Wo, W1, W2,
                                                 QKVWHL, WOHL, W1HL, W2HL);

    embed_kernel<<<MM, 128>>>(seq, W_emb, b_emb, pos, X, XHL);

    dim3 gQKV(1536 / 128, MM / 64);   // 768 CTAs
    dim3 gE(EE / 128, MM / 64);       // 256 CTAs
    dim3 gF(FFN / 128, MM / 64);      // 1024 CTAs
    dim3 attnG(SS / 128, BB * HH);

    for (int l = 0; l < LL; l++) {
        size_t oB = (size_t)l * EE, oB1 = (size_t)l * FFN;

        hl_gemm<2><<<gQKV, 256, GSMEM>>>(XHL, QKVWHL + (size_t)l * 1536 * 2 * EE,
                                         bqkv + (size_t)l * 1536, nullptr, 0, EE,
                                         Qh, Ql, Kh, Kl, VhT, VlT);
        attn_hmma<<<attnG, 256, ATTN_SMEM2>>>(Qh, Ql, Kh, Kl, VhT, VlT, mask, ATTHL);

        hl_gemm<0><<<gE, 256, GSMEM>>>(ATTHL, WOHL + (size_t)l * EE * 2 * EE, bo + oB, P, EE, EE,
                                       nullptr, nullptr, nullptr, nullptr, nullptr, nullptr);
        ln_kernel<<<MM / 2, 256>>>(X, P, ln1g + oB, ln1b + oB, X, XHL);

        hl_gemm<1><<<gF, 256, GSMEM>>>(XHL, W1HL + (size_t)l * FFN * 2 * EE, b1 + oB1, H1HL, FFN, EE,
                                       nullptr, nullptr, nullptr, nullptr, nullptr, nullptr);
        hl_gemm<0><<<gE, 256, GSMEM>>>(H1HL, W2HL + (size_t)l * EE * 2 * FFN, b2 + oB, P, EE, FFN,
                                       nullptr, nullptr, nullptr, nullptr, nullptr, nullptr);

        float* dst = (l == LL - 1) ? out : X;
        ln_kernel<<<MM / 2, 256>>>(X, P, ln2g + oB, ln2b + oB, dst, (l == LL - 1) ? nullptr : XHL);
    }
}

// round 14
// speedup vs baseline: 1.3850x; 1.3850x over previous
#include <cuda_runtime.h>
#include <cuda_fp16.h>
#include <math.h>
#include <stdint.h>

#define BB 2
#define SS 2048
#define FF_IN 64
#define EE 512
#define HH 8
#define DH 64
#define LL 4
#define FFN 2048
#define MM (BB * SS)
#define ATTN_SCALE 0.044194173824159216f

// ---------------- helpers ----------------
__device__ __forceinline__ uint32_t smem_u32(const void* p) {
    uint32_t a;
    asm("{ .reg .u64 t; cvta.to.shared.u64 t, %1; cvt.u32.u64 %0, t; }" : "=r"(a) : "l"(p));
    return a;
}
#define SWZ128(o) ((o) ^ (((o) >> 3) & 0x70))

__device__ __forceinline__ void cp16(uint32_t s, const void* g) {
    asm volatile("cp.async.cg.shared.global [%0], [%1], 16;" :: "r"(s), "l"(g) : "memory");
}
#define CP_COMMIT() asm volatile("cp.async.commit_group;" ::: "memory")

__device__ __forceinline__ void ldsm4(uint32_t* d, uint32_t a) {
    asm volatile("ldmatrix.sync.aligned.m8n8.x4.shared.b16 {%0,%1,%2,%3}, [%4];"
                 : "=r"(d[0]), "=r"(d[1]), "=r"(d[2]), "=r"(d[3]) : "r"(a));
}
__device__ __forceinline__ void mma_f16(float* c, const uint32_t* a, const uint32_t* b) {
    asm volatile("mma.sync.aligned.m16n8k16.row.col.f32.f16.f16.f32 "
        "{%0,%1,%2,%3}, {%4,%5,%6,%7}, {%8,%9}, {%0,%1,%2,%3};"
        : "+f"(c[0]), "+f"(c[1]), "+f"(c[2]), "+f"(c[3])
        : "r"(a[0]), "r"(a[1]), "r"(a[2]), "r"(a[3]), "r"(b[0]), "r"(b[1]));
}

__device__ __forceinline__ void split_hl(float f, uint16_t& h, uint16_t& l) {
    __half hb = __float2half_rn(f);
    __half lb = __float2half_rn(f - __half2float(hb));
    h = __half_as_ushort(hb); l = __half_as_ushort(lb);
}
__device__ __forceinline__ uint16_t to_h(float f) {
    return __half_as_ushort(__float2half_rn(f));
}
__device__ __forceinline__ uint32_t pack2(uint16_t a, uint16_t b) {
    return (uint32_t)a | ((uint32_t)b << 16);
}
// A-side HL row: K/32 blocks of 64 halfs (32 hi | 32 lo)
__device__ __forceinline__ void store_hl4(__half* rowp, int col,
                                          float v0, float v1, float v2, float v3) {
    int b = col >> 5, w = col & 31;
    uint16_t h0,l0,h1,l1,h2,l2,h3,l3;
    split_hl(v0,h0,l0); split_hl(v1,h1,l1); split_hl(v2,h2,l2); split_hl(v3,h3,l3);
    *(uint2*)(rowp + b*64 + w)      = make_uint2(pack2(h0,h1), pack2(h2,h3));
    *(uint2*)(rowp + b*64 + 32 + w) = make_uint2(pack2(l0,l1), pack2(l2,l3));
}
__device__ __forceinline__ void store_hl2(__half* rowp, int col, float v0, float v1) {
    int b = col >> 5, w = col & 31;
    uint16_t h0,l0,h1,l1;
    split_hl(v0,h0,l0); split_hl(v1,h1,l1);
    *(uint32_t*)(rowp + b*64 + w)      = pack2(h0,h1);
    *(uint32_t*)(rowp + b*64 + 32 + w) = pack2(l0,l1);
}

// ---------------- scratch ----------------
__device__ float g_X[MM * EE];
__device__ float g_P[MM * EE];
__device__ float g_bqkv[LL * 1536];
__device__ __half g_XHL[MM * 2 * EE];
__device__ __half g_ATTHL[MM * 2 * EE];
__device__ __half g_H1HL[MM * 2 * FFN];
__device__ __half g_Qh[MM * EE], g_Ql[MM * EE];
__device__ __half g_Kh[MM * EE];
__device__ __half g_VhT[BB * HH * DH * SS];
__device__ __half g_QKVW[LL * 1536 * EE];
__device__ __half g_WO[LL * EE * EE];
__device__ __half g_W1[LL * FFN * EE];
__device__ __half g_W2[LL * EE * FFN];

// ---------------- merged weight prep: W[K][N] fp32 -> D[N][K] fp16 ----------------
__global__ __launch_bounds__(256) void prep_all(
    const float* __restrict__ Wq, const float* __restrict__ Wk,
    const float* __restrict__ Wv, const float* __restrict__ Wo,
    const float* __restrict__ W1, const float* __restrict__ W2,
    __half* __restrict__ QKVW, __half* __restrict__ WOp,
    __half* __restrict__ W1p, __half* __restrict__ W2p)
{
    __shared__ float t[32][33];
    int bid = blockIdx.x, l = blockIdx.z;
    const float* W; __half* D; int K, N, bx, by;
    if (bid < 1024) {
        int s = bid >> 8; bid &= 255;
        K = EE; N = EE; bx = bid & 15; by = bid >> 4;
        const float* srcs[4] = {Wq, Wk, Wv, Wo};
        W = srcs[s] + (size_t)l * EE * EE;
        D = (s < 3) ? QKVW + (size_t)l * 1536 * EE + (size_t)s * 512 * EE
                    : WOp + (size_t)l * EE * EE;
    } else if (bid < 2048) {
        bid -= 1024;
        K = EE; N = FFN; bx = bid & 63; by = bid >> 6;
        W = W1 + (size_t)l * EE * FFN;
        D = W1p + (size_t)l * FFN * EE;
    } else {
        bid -= 2048;
        K = FFN; N = EE; bx = bid & 15; by = bid >> 4;
        W = W2 + (size_t)l * FFN * EE;
        D = W2p + (size_t)l * EE * FFN;
    }
    int k0 = by * 32, n0 = bx * 32;
    int tx = threadIdx.x, ty = threadIdx.y;
    #pragma unroll
    for (int i = 0; i < 4; i++)
        t[ty + i * 8][tx] = W[(size_t)(k0 + ty + i * 8) * N + n0 + tx];
    __syncthreads();
    #pragma unroll
    for (int i = 0; i < 4; i++) {
        int n = n0 + ty + i * 8;
        D[(size_t)n * K + k0 + tx] = __float2half_rn(t[tx][ty + i * 8]);
    }
}

__global__ __launch_bounds__(256) void biascat_kernel(
    const float* __restrict__ bq, const float* __restrict__ bk,
    const float* __restrict__ bv, float* __restrict__ o)
{
    int i = blockIdx.x * 256 + threadIdx.x;
    if (i >= LL * 1536) return;
    int l = i / 1536, j = i - l * 1536;
    o[i] = (j < 512) ? bq[l * 512 + j] : (j < 1024) ? bk[l * 512 + j - 512] : bv[l * 512 + j - 1024];
}

// ---------------- fp16 2-term HMMA GEMM ----------------
// A: HL row (4K bytes/row); B: plain [N][K] fp16 (2K bytes/row).
// Stage = 64 logical k: A two 128B blocks/row (block-major), B one 128B row.
// MT: M-tile = 64*MT. Stage bytes = (MT+1)*16KB; 2 stages.
template <int OUTQ, int MT>
__global__ __launch_bounds__(256, 2) void hl_gemm(
    const __half* __restrict__ A, const __half* __restrict__ B,
    const float* __restrict__ bias, void* __restrict__ Cout, int ldc, int K,
    __half* __restrict__ qh, __half* __restrict__ ql,
    __half* __restrict__ kh, __half* __restrict__ vth)
{
    extern __shared__ char smem[];
    const uint32_t sb = smem_u32(smem);
    const int STB = (MT + 1) * 16384;
    const int tid = threadIdx.x, lane = tid & 31, wid = tid >> 5;
    const int wm = (wid >> 1) * 16 * MT, wn = (wid & 1) * 64;
    const int cRow = blockIdx.y * 64 * MT, cCol = blockIdx.x * 128;
    const size_t rowA = (size_t)K * 4;   // bytes
    const size_t rowB = (size_t)K * 2;
    const char* Abase = (const char*)(A + (size_t)cRow * 2 * K);
    const char* Bbase = (const char*)(B + (size_t)cCol * K);

    float acc[MT][8][4];
    #pragma unroll
    for (int a = 0; a < MT; a++)
        #pragma unroll
        for (int b = 0; b < 8; b++)
            #pragma unroll
            for (int c = 0; c < 4; c++) acc[a][b][c] = 0.f;

    uint32_t oA[MT], oB4[4];
    #pragma unroll
    for (int mt = 0; mt < MT; mt++) {
        int row = wm + mt * 16 + ((lane >> 3) & 1) * 8 + (lane & 7);
        oA[mt] = SWZ128((uint32_t)(row * 128 + (lane >> 4) * 16));
    }
    #pragma unroll
    for (int ng = 0; ng < 4; ng++) {
        int row = wn + ng * 16 + ((lane >> 4) & 1) * 8 + (lane & 7);
        oB4[ng] = SWZ128((uint32_t)(row * 128 + ((lane >> 3) & 1) * 16));
    }

    const int lr = tid >> 3, lc = (tid & 7) * 16;
    auto load_stage = [&](int s) {
        uint32_t dA = sb + (s & 1) * STB, dB = dA + MT * 16384;
        size_t kbA = (size_t)s * 256, kbB = (size_t)s * 128;
        #pragma unroll
        for (int j = 0; j < 2; j++)
            #pragma unroll
            for (int i = 0; i < 2 * MT; i++) {
                int r = lr + i * 32;
                cp16(dA + j * MT * 8192 + SWZ128(r * 128 + lc),
                     Abase + (size_t)r * rowA + kbA + j * 128 + lc);
            }
        #pragma unroll
        for (int i = 0; i < 4; i++) {
            int r = lr + i * 32;
            cp16(dB + SWZ128(r * 128 + lc), Bbase + (size_t)r * rowB + kbB + lc);
        }
    };

    const int NS = K / 64;
    load_stage(0); CP_COMMIT();
    for (int s = 0; s < NS; s++) {
        if (s + 1 < NS) {
            load_stage(s + 1); CP_COMMIT();
            asm volatile("cp.async.wait_group 1;" ::: "memory");
        } else {
            asm volatile("cp.async.wait_group 0;" ::: "memory");
        }
        __syncthreads();
        uint32_t sA = sb + (s & 1) * STB, sB = sA + MT * 16384;
        #pragma unroll
        for (int kc = 0; kc < 4; kc++) {
            const uint32_t blkofs = (kc >> 1) * (MT * 8192);
            const uint32_t ch = (kc & 1) * 32, cl = 64 + (kc & 1) * 32;
            const uint32_t bc = kc * 32;
            uint32_t ah[MT][4], al[MT][4];
            #pragma unroll
            for (int mt = 0; mt < MT; mt++) {
                ldsm4(ah[mt], sA + blkofs + (oA[mt] ^ ch));
                ldsm4(al[mt], sA + blkofs + (oA[mt] ^ cl));
            }
            #pragma unroll
            for (int ng = 0; ng < 4; ng++) {
                uint32_t bh[4];
                ldsm4(bh, sB + (oB4[ng] ^ bc));
                #pragma unroll
                for (int term = 0; term < 2; term++)
                    #pragma unroll
                    for (int t2 = 0; t2 < 2; t2++) {
                        int nt = ng * 2 + t2;
                        #pragma unroll
                        for (int mt = 0; mt < MT; mt++)
                            mma_f16(acc[mt][nt], term ? al[mt] : ah[mt], &bh[t2 * 2]);
                    }
            }
        }
        __syncthreads();
    }

    if (OUTQ == 2 && cCol >= 1024) {
        // V tile: stage hi plane [col][row], write transposed
        const int R = 64 * MT, P = R + 4;
        uint16_t* shi = (uint16_t*)smem;
        #pragma unroll
        for (int mt = 0; mt < MT; mt++)
            #pragma unroll
            for (int rp = 0; rp < 2; rp++) {
                int lrw = wm + mt * 16 + rp * 8 + (lane >> 2);
                #pragma unroll
                for (int nt = 0; nt < 8; nt++) {
                    int clw = wn + nt * 8 + (lane & 3) * 2;
                    float2 bz = *(const float2*)(bias + cCol + clw);
                    shi[clw * P + lrw]       = to_h(acc[mt][nt][rp * 2]     + bz.x);
                    shi[(clw + 1) * P + lrw] = to_h(acc[mt][nt][rp * 2 + 1] + bz.y);
                }
            }
        __syncthreads();
        int c = tid >> 1, rh = (tid & 1) * (R / 2);
        int gcol = cCol - 1024 + c;
        int hh = gcol >> 6, d = gcol & 63;
        int b = cRow >> 11, s0 = (cRow & 2047) + rh;
        __half* dh = vth + ((size_t)(b * HH + hh) * DH + d) * SS + s0;
        const uint16_t* sh = shi + c * P + rh;
        #pragma unroll
        for (int i = 0; i < R / 8; i++)
            *(uint2*)(dh + i * 4) = *(const uint2*)(sh + i * 4);
        return;
    }

    #pragma unroll
    for (int mt = 0; mt < MT; mt++)
        #pragma unroll
        for (int rp = 0; rp < 2; rp++) {
            int row = cRow + wm + mt * 16 + rp * 8 + (lane >> 2);
            #pragma unroll
            for (int nt = 0; nt < 8; nt++) {
                int col = cCol + wn + nt * 8 + (lane & 3) * 2;
                float2 bz = *(const float2*)(bias + col);
                float v0 = acc[mt][nt][rp * 2]     + bz.x;
                float v1 = acc[mt][nt][rp * 2 + 1] + bz.y;
                if (OUTQ == 1) {
                    v0 = fmaxf(v0, 0.f); v1 = fmaxf(v1, 0.f);
                    store_hl2((__half*)Cout + (size_t)row * 2 * ldc, col, v0, v1);
                } else if (OUTQ == 2) {
                    if (col < 512) {
                        float s0 = v0 * ATTN_SCALE, s1 = v1 * ATTN_SCALE;
                        uint16_t h0, l0, h1, l1;
                        split_hl(s0, h0, l0); split_hl(s1, h1, l1);
                        *(uint32_t*)(qh + (size_t)row * EE + col) = pack2(h0, h1);
                        *(uint32_t*)(ql + (size_t)row * EE + col) = pack2(l0, l1);
                    } else {
                        int cc = col - 512;
                        *(uint32_t*)(kh + (size_t)row * EE + cc) = pack2(to_h(v0), to_h(v1));
                    }
                } else {
                    *(float2*)((float*)Cout + (size_t)row * ldc + col) = make_float2(v0, v1);
                }
            }
        }
}

// ---------------- fp16 HMMA flash attention ----------------
// Q hi/lo planes persist (32KB); stages: Kh 8KB + Vh 8KB, double buffered.
#define ATTN_SMEM2 (65536 + 512)
__global__ __launch_bounds__(256, 2) void attn_hmma(
    const __half* __restrict__ Qh, const __half* __restrict__ Ql,
    const __half* __restrict__ Kh, const __half* __restrict__ VhT,
    const int* __restrict__ mask, __half* __restrict__ ATTHL)
{
    extern __shared__ char smem[];
    const uint32_t sb = smem_u32(smem);
    int* Ms = (int*)(smem + 65536);
    const int tid = threadIdx.x, lane = tid & 31, wid = tid >> 5;
    const int bh = blockIdx.y, b = bh >> 3, h = bh & 7;
    const int qrow0 = blockIdx.x * 128;
    const int wr = wid * 16;

    uint32_t oQ, oKV[4];
    {
        int row = wr + ((lane >> 3) & 1) * 8 + (lane & 7);
        oQ = SWZ128((uint32_t)(row * 128 + (lane >> 4) * 16));
    }
    #pragma unroll
    for (int ng = 0; ng < 4; ng++) {
        int row = ng * 16 + ((lane >> 4) & 1) * 8 + (lane & 7);
        oKV[ng] = SWZ128((uint32_t)(row * 128 + ((lane >> 3) & 1) * 16));
    }

    {
        const char* qhp = (const char*)(Qh + (size_t)(b * SS + qrow0) * EE + h * DH);
        const char* qlp = (const char*)(Ql + (size_t)(b * SS + qrow0) * EE + h * DH);
        #pragma unroll
        for (int i = 0; i < 4; i++) {
            int id = tid + i * 256;
            int r = id >> 3, ck = (id & 7) * 16;
            cp16(sb +         SWZ128(r * 128 + ck), qhp + (size_t)r * 1024 + ck);
            cp16(sb + 16384 + SWZ128(r * 128 + ck), qlp + (size_t)r * 1024 + ck);
        }
    }
    auto load_stage = [&](int kt) {
        uint32_t st = sb + 32768 + (kt & 1) * 16384;
        const char* khp = (const char*)(Kh + (size_t)(b * SS + kt * 64) * EE + h * DH);
        const char* vhp = (const char*)(VhT + (size_t)bh * DH * SS + kt * 64);
        #pragma unroll
        for (int i = 0; i < 2; i++) {
            int r = (tid >> 3) + i * 32, ck = (tid & 7) * 16;
            cp16(st +        SWZ128(r * 128 + ck), khp + (size_t)r * 1024 + ck);
            cp16(st + 8192 + SWZ128(r * 128 + ck), vhp + (size_t)r * (SS * 2) + ck);
        }
        if (tid < 64) Ms[(kt & 1) * 64 + tid] = mask[b * SS + kt * 64 + tid];
    };

    float m_i[2] = {-INFINITY, -INFINITY}, l_i[2] = {0.f, 0.f};
    float o_acc[8][4];
    #pragma unroll
    for (int nt = 0; nt < 8; nt++)
        #pragma unroll
        for (int c = 0; c < 4; c++) o_acc[nt][c] = 0.f;

    load_stage(0); CP_COMMIT();
    const int NT = SS / 64;
    for (int kt = 0; kt < NT; kt++) {
        if (kt + 1 < NT) {
            load_stage(kt + 1); CP_COMMIT();
            asm volatile("cp.async.wait_group 1;" ::: "memory");
        } else {
            asm volatile("cp.async.wait_group 0;" ::: "memory");
        }
        __syncthreads();
        const uint32_t st = sb + 32768 + (kt & 1) * 16384;
        const uint32_t sKh = st, sVh = st + 8192;

        float s_acc[8][4];
        #pragma unroll
        for (int nt = 0; nt < 8; nt++)
            #pragma unroll
            for (int c = 0; c < 4; c++) s_acc[nt][c] = 0.f;

        #pragma unroll
        for (int kc = 0; kc < 4; kc++) {
            const uint32_t bc = kc * 32;
            uint32_t qhf[4], qlf[4];
            ldsm4(qhf, sb +         (oQ ^ bc));
            ldsm4(qlf, sb + 16384 + (oQ ^ bc));
            #pragma unroll
            for (int ng = 0; ng < 4; ng++) {
                uint32_t khf[4];
                ldsm4(khf, sKh + (oKV[ng] ^ bc));
                #pragma unroll
                for (int term = 0; term < 2; term++)
                    #pragma unroll
                    for (int t2 = 0; t2 < 2; t2++) {
                        int nt = ng * 2 + t2;
                        mma_f16(s_acc[nt], term ? qlf : qhf, &khf[t2 * 2]);
                    }
            }
        }

        const int t4 = (lane & 3) * 2;
        const int msb = (kt & 1) * 64;
        #pragma unroll
        for (int nt = 0; nt < 8; nt++) {
            if (Ms[msb + nt * 8 + t4] == 0)     { s_acc[nt][0] = -1e20f; s_acc[nt][2] = -1e20f; }
            if (Ms[msb + nt * 8 + t4 + 1] == 0) { s_acc[nt][1] = -1e20f; s_acc[nt][3] = -1e20f; }
        }

        #pragma unroll
        for (int r = 0; r < 2; r++) {
            float mx = -INFINITY;
            #pragma unroll
            for (int nt = 0; nt < 8; nt++)
                mx = fmaxf(mx, fmaxf(s_acc[nt][r * 2], s_acc[nt][r * 2 + 1]));
            mx = fmaxf(mx, __shfl_xor_sync(0xffffffffu, mx, 1));
            mx = fmaxf(mx, __shfl_xor_sync(0xffffffffu, mx, 2));
            float mnew = fmaxf(m_i[r], mx);
            float corr = __expf(m_i[r] - mnew);
            float rs = 0.f;
            #pragma unroll
            for (int nt = 0; nt < 8; nt++) {
                float p0 = __expf(s_acc[nt][r * 2] - mnew);
                float p1 = __expf(s_acc[nt][r * 2 + 1] - mnew);
                s_acc[nt][r * 2] = p0; s_acc[nt][r * 2 + 1] = p1;
                rs += p0 + p1;
            }
            rs += __shfl_xor_sync(0xffffffffu, rs, 1);
            rs += __shfl_xor_sync(0xffffffffu, rs, 2);
            l_i[r] = l_i[r] * corr + rs;
            m_i[r] = mnew;
            #pragma unroll
            for (int nt = 0; nt < 8; nt++) {
                o_acc[nt][r * 2] *= corr; o_acc[nt][r * 2 + 1] *= corr;
            }
        }

        #pragma unroll
        for (int kc = 0; kc < 4; kc++) {
            const uint32_t bc = kc * 32;
            uint32_t ph[4], pl[4];
            {
                uint16_t h0, l0, h1, l1;
                split_hl(s_acc[2 * kc][0], h0, l0); split_hl(s_acc[2 * kc][1], h1, l1);
                ph[0] = pack2(h0, h1); pl[0] = pack2(l0, l1);
                split_hl(s_acc[2 * kc][2], h0, l0); split_hl(s_acc[2 * kc][3], h1, l1);
                ph[1] = pack2(h0, h1); pl[1] = pack2(l0, l1);
                split_hl(s_acc[2 * kc + 1][0], h0, l0); split_hl(s_acc[2 * kc + 1][1], h1, l1);
                ph[2] = pack2(h0, h1); pl[2] = pack2(l0, l1);
                split_hl(s_acc[2 * kc + 1][2], h0, l0); split_hl(s_acc[2 * kc + 1][3], h1, l1);
                ph[3] = pack2(h0, h1); pl[3] = pack2(l0, l1);
            }
            #pragma unroll
            for (int ng = 0; ng < 4; ng++) {
                uint32_t vhf[4];
                ldsm4(vhf, sVh + (oKV[ng] ^ bc));
                #pragma unroll
                for (int term = 0; term < 2; term++)
                    #pragma unroll
                    for (int t2 = 0; t2 < 2; t2++) {
                        int nt = ng * 2 + t2;
                        mma_f16(o_acc[nt], term ? pl : ph, &vhf[t2 * 2]);
                    }
            }
        }
        __syncthreads();
    }

    const int g = lane >> 2;
    #pragma unroll
    for (int r = 0; r < 2; r++) {
        float inv = 1.f / l_i[r];
        int row = qrow0 + wr + g + r * 8;
        __half* rp = ATTHL + (size_t)(b * SS + row) * 2 * EE;
        #pragma unroll
        for (int nt = 0; nt < 8; nt++) {
            int col = h * DH + nt * 8 + (lane & 3) * 2;
            store_hl2(rp, col, o_acc[nt][r * 2] * inv, o_acc[nt][r * 2 + 1] * inv);
        }
    }
}

// ---------------- embedding ----------------
__global__ __launch_bounds__(128) void embed_kernel(
    const float* __restrict__ seq, const float* __restrict__ W,
    const float* __restrict__ bias, const float* __restrict__ pos,
    float* __restrict__ X, __half* __restrict__ XHL)
{
    int m = blockIdx.x, s = m & (SS - 1), tid = threadIdx.x;
    __shared__ float srow[FF_IN];
    if (tid < FF_IN) srow[tid] = seq[(size_t)m * FF_IN + tid];
    __syncthreads();
    int n = tid * 4;
    float4 acc = *(const float4*)(bias + n);
    float4 pv  = *(const float4*)(pos + (size_t)s * EE + n);
    acc.x += pv.x; acc.y += pv.y; acc.z += pv.z; acc.w += pv.w;
    #pragma unroll 8
    for (int f = 0; f < FF_IN; f++) {
        float sv = srow[f];
        float4 w = *(const float4*)(W + (size_t)f * EE + n);
        acc.x += sv * w.x; acc.y += sv * w.y; acc.z += sv * w.z; acc.w += sv * w.w;
    }
    *(float4*)(X + (size_t)m * EE + n) = acc;
    store_hl4(XHL + (size_t)m * 2 * EE, n, acc.x, acc.y, acc.z, acc.w);
}

// ---------------- residual + LN (2 rows per 256-thread block) ----------------
__global__ __launch_bounds__(256) void ln_kernel(
    const float* __restrict__ a, const float* __restrict__ br,
    const float* __restrict__ g, const float* __restrict__ be,
    float* __restrict__ out, __half* __restrict__ xhl)
{
    int tid = threadIdx.x;
    int rloc = tid >> 7;
    int t = tid & 127;
    int m = blockIdx.x * 2 + rloc;
    size_t base = (size_t)m * EE + t * 4;
    float4 va = *(const float4*)(a + base);
    float4 vb = *(const float4*)(br + base);
    float x0 = va.x + vb.x, x1 = va.y + vb.y, x2 = va.z + vb.z, x3 = va.w + vb.w;
    float s = x0 + x1 + x2 + x3;
    float ss = x0 * x0 + x1 * x1 + x2 * x2 + x3 * x3;
    #pragma unroll
    for (int off = 16; off; off >>= 1) {
        s  += __shfl_xor_sync(0xffffffffu, s, off);
        ss += __shfl_xor_sync(0xffffffffu, ss, off);
    }
    __shared__ float red[2][8];
    int w = t >> 5;
    if ((t & 31) == 0) { red[rloc][w] = s; red[rloc][4 + w] = ss; }
    __syncthreads();
    s  = red[rloc][0] + red[rloc][1] + red[rloc][2] + red[rloc][3];
    ss = red[rloc][4] + red[rloc][5] + red[rloc][6] + red[rloc][7];
    float mean = s * (1.f / EE);
    float var  = ss * (1.f / EE) - mean * mean;
    float r = rsqrtf(var + 1e-5f);
    float4 gg = *(const float4*)(g + t * 4);
    float4 bb = *(const float4*)(be + t * 4);
    float4 o;
    o.x = (x0 - mean) * r * gg.x + bb.x;
    o.y = (x1 - mean) * r * gg.y + bb.y;
    o.z = (x2 - mean) * r * gg.z + bb.z;
    o.w = (x3 - mean) * r * gg.w + bb.w;
    *(float4*)(out + base) = o;
    if (xhl) store_hl4(xhl + (size_t)m * 2 * EE, t * 4, o.x, o.y, o.z, o.w);
}

// ---------------- launch ----------------
#define GSMEM1 65536
#define GSMEM2 98304
extern "C" void kernel_launch(void* const* d_in, const int* in_sizes, int n_in,
                              void* d_out, int out_size)
{
    const float* seq   = (const float*)d_in[0];
    const int*   mask  = (const int*)  d_in[1];
    const float* W_emb = (const float*)d_in[2];
    const float* b_emb = (const float*)d_in[3];
    const float* pos   = (const float*)d_in[4];
    const float* Wq    = (const float*)d_in[5];
    const float* bq    = (const float*)d_in[6];
    const float* Wk    = (const float*)d_in[7];
    const float* bk    = (const float*)d_in[8];
    const float* Wv    = (const float*)d_in[9];
    const float* bv    = (const float*)d_in[10];
    const float* Wo    = (const float*)d_in[11];
    const float* bo    = (const float*)d_in[12];
    const float* ln1g  = (const float*)d_in[13];
    const float* ln1b  = (const float*)d_in[14];
    const float* ln2g  = (const float*)d_in[15];
    const float* ln2b  = (const float*)d_in[16];
    const float* W1    = (const float*)d_in[17];
    const float* b1    = (const float*)d_in[18];
    const float* W2    = (const float*)d_in[19];
    const float* b2    = (const float*)d_in[20];
    float* out = (float*)d_out;

    float *X, *P, *bqkv;
    __half *XHL, *ATTHL, *H1HL, *QKVW, *WOp, *W1p, *W2p;
    __half *Qh, *Ql, *Kh, *VhT;
    cudaGetSymbolAddress((void**)&X,     g_X);
    cudaGetSymbolAddress((void**)&P,     g_P);
    cudaGetSymbolAddress((void**)&bqkv,  g_bqkv);
    cudaGetSymbolAddress((void**)&XHL,   g_XHL);
    cudaGetSymbolAddress((void**)&ATTHL, g_ATTHL);
    cudaGetSymbolAddress((void**)&H1HL,  g_H1HL);
    cudaGetSymbolAddress((void**)&QKVW,  g_QKVW);
    cudaGetSymbolAddress((void**)&WOp,   g_WO);
    cudaGetSymbolAddress((void**)&W1p,   g_W1);
    cudaGetSymbolAddress((void**)&W2p,   g_W2);
    cudaGetSymbolAddress((void**)&Qh,    g_Qh);
    cudaGetSymbolAddress((void**)&Ql,    g_Ql);
    cudaGetSymbolAddress((void**)&Kh,    g_Kh);
    cudaGetSymbolAddress((void**)&VhT,   g_VhT);

    cudaFuncSetAttribute((const void*)hl_gemm<0, 1>, cudaFuncAttributeMaxDynamicSharedMemorySize, GSMEM1);
    cudaFuncSetAttribute((const void*)hl_gemm<1, 2>, cudaFuncAttributeMaxDynamicSharedMemorySize, GSMEM2);
    cudaFuncSetAttribute((const void*)hl_gemm<2, 1>, cudaFuncAttributeMaxDynamicSharedMemorySize, GSMEM1);
    cudaFuncSetAttribute((const void*)attn_hmma, cudaFuncAttributeMaxDynamicSharedMemorySize, ATTN_SMEM2);

    biascat_kernel<<<24, 256>>>(bq, bk, bv, bqkv);
    prep_all<<<dim3(3072, 1, LL), dim3(32, 8)>>>(Wq, Wk, Wv, Wo, W1, W2,
                                                 QKVW, WOp, W1p, W2p);

    embed_kernel<<<MM, 128>>>(seq, W_emb, b_emb, pos, X, XHL);

    dim3 gQKV(1536 / 128, MM / 64);   // MT=1
    dim3 gE(EE / 128, MM / 64);       // MT=1
    dim3 gF(FFN / 128, MM / 128);     // MT=2
    dim3 attnG(SS / 128, BB * HH);

    for (int l = 0; l < LL; l++) {
        size_t oB = (size_t)l * EE, oB1 = (size_t)l * FFN;

        hl_gemm<2, 1><<<gQKV, 256, GSMEM1>>>(XHL, QKVW + (size_t)l * 1536 * EE,
                                             bqkv + (size_t)l * 1536, nullptr, 0, EE,
                                             Qh, Ql, Kh, VhT);
        attn_hmma<<<attnG, 256, ATTN_SMEM2>>>(Qh, Ql, Kh, VhT, mask, ATTHL);

        hl_gemm<0, 1><<<gE, 256, GSMEM1>>>(ATTHL, WOp + (size_t)l * EE * EE, bo + oB, P, EE, EE,
                                           nullptr, nullptr, nullptr, nullptr);
        ln_kernel<<<MM / 2, 256>>>(X, P, ln1g + oB, ln1b + oB, X, XHL);

        hl_gemm<1, 2><<<gF, 256, GSMEM2>>>(XHL, W1p + (size_t)l * FFN * EE, b1 + oB1, H1HL, FFN, EE,
                                           nullptr, nullptr, nullptr, nullptr);
        hl_gemm<0, 1><<<gE, 256, GSMEM1>>>(H1HL, W2p + (size_t)l * EE * FFN, b2 + oB, P, EE, FFN,
                                           nullptr, nullptr, nullptr, nullptr);

        float* dst = (l == LL - 1) ? out : X;
        ln_kernel<<<MM / 2, 256>>>(X, P, ln2g + oB, ln2b + oB, dst, (l == LL - 1) ? nullptr : XHL);
    }
}